// round 15
// baseline (speedup 1.0000x reference)
#include <cuda_runtime.h>
#include <cuda_fp16.h>
#include <cstdint>

#define NB   4
#define LL   2048
#define HH   16
#define DD   64
#define EE   1024

// ---------- mma / ldmatrix / cp.async helpers (portable sm_80-class PTX) ----------
static __device__ __forceinline__ uint32_t smem_u32(const void* p) {
    uint32_t a;
    asm("{ .reg .u64 t; cvta.to.shared.u64 t, %1; cvt.u32.u64 %0, t; }" : "=r"(a) : "l"(p));
    return a;
}
static __device__ __forceinline__ void mma_f16(float* d, const uint32_t* a, const uint32_t* b) {
    asm volatile("mma.sync.aligned.m16n8k16.row.col.f32.f16.f16.f32 "
        "{%0,%1,%2,%3}, {%4,%5,%6,%7}, {%8,%9}, {%0,%1,%2,%3};"
        : "+f"(d[0]), "+f"(d[1]), "+f"(d[2]), "+f"(d[3])
        : "r"(a[0]), "r"(a[1]), "r"(a[2]), "r"(a[3]), "r"(b[0]), "r"(b[1]));
}
static __device__ __forceinline__ void ldsm4(uint32_t* r, uint32_t addr) {
    asm volatile("ldmatrix.sync.aligned.m8n8.x4.shared.b16 {%0,%1,%2,%3}, [%4];"
        : "=r"(r[0]), "=r"(r[1]), "=r"(r[2]), "=r"(r[3]) : "r"(addr));
}
static __device__ __forceinline__ void ldsm4t(uint32_t* r, uint32_t addr) {
    asm volatile("ldmatrix.sync.aligned.m8n8.x4.trans.shared.b16 {%0,%1,%2,%3}, [%4];"
        : "=r"(r[0]), "=r"(r[1]), "=r"(r[2]), "=r"(r[3]) : "r"(addr));
}
static __device__ __forceinline__ void cpa16(uint32_t dst, const void* src) {
    asm volatile("cp.async.cg.shared.global [%0], [%1], 16;" :: "r"(dst), "l"(src) : "memory");
}
#define CP_COMMIT()  asm volatile("cp.async.commit_group;" ::: "memory")
#define CP_WAITG(n)  asm volatile("cp.async.wait_group %0;" :: "n"(n) : "memory")

static __device__ __forceinline__ uint32_t packh2(float a, float b) {
    __half2 h = __floats2half2_rn(a, b);
    return *(uint32_t*)&h;
}
static __device__ __forceinline__ uint32_t ex2h2(uint32_t s) {
    uint32_t p;
    asm("ex2.approx.f16x2 %0, %1;" : "=r"(p) : "r"(s));
    return p;
}

// 128B-row xor swizzle on 16B chunks (r = row, c = 16B chunk 0..7)
#define SWZ(r, c) ((uint32_t)((r) * 128 + (((c) ^ ((r) & 7)) << 4)))

#define QSCALE (0.03125f * 1.4426950408889634f)
#define ONESH2 0x3C003C00u

// Output-staging row stride: 144B => conflict-free fragment stores.
#define STGS 144

// ---------- device scratch ----------
__device__ __half g_wh[3 * 64 * 64];
__device__ __half g_qh[NB * HH * LL * DD];
__device__ __half g_kh[NB * HH * LL * DD];
__device__ __half g_vh[NB * HH * LL * DD];
__device__ __half g_ctxh[NB * LL * EE];
__device__ __half g_woh[EE * EE];

// =====================================================================
// Kernel 0: fp32 -> fp16 conversion of Wo and the QKV weights (small).
// =====================================================================
__global__ void __launch_bounds__(256) convert_kernel(
    const float* __restrict__ Wq,
    const float* __restrict__ Wk,
    const float* __restrict__ Wv,
    const float* __restrict__ Wo)
{
    int b = blockIdx.x;
    if (b < 1024) {
        int i = b * 256 + threadIdx.x;
        float4 v = ((const float4*)Wo)[i];
        ((__half2*)g_woh)[2 * i]     = __floats2half2_rn(v.x, v.y);
        ((__half2*)g_woh)[2 * i + 1] = __floats2half2_rn(v.z, v.w);
    } else {
        const float* Ws[3] = {Wq, Wk, Wv};
        #pragma unroll
        for (int m = 0; m < 3; ++m) {
            float sc = (m == 0) ? QSCALE : 1.0f;
            for (int i = threadIdx.x; i < 1024; i += 256) {
                float4 v = ((const float4*)Ws[m])[i];
                ((__half2*)(g_wh + m * 4096))[2 * i]     = __floats2half2_rn(v.x * sc, v.y * sc);
                ((__half2*)(g_wh + m * 4096))[2 * i + 1] = __floats2half2_rn(v.z * sc, v.w * sc);
            }
        }
    }
}

// =====================================================================
// Kernel 1: QKV flat GEMM with ping-pong x tiles (256 rows/CTA, 512 CTAs).
// Tile t+1 loads while tile t computes/stores. smem: W 24KB | 2 x-bufs
// 36KB each | staging 18KB = 114KB -> 2 CTAs/SM.
// =====================================================================
#define XSTRIDE 72
#define XBUF    (128 * XSTRIDE * 4)
#define XOFF    24576
#define STG_OFF (XOFF + 2 * XBUF)
#define QKV_SMEM (STG_OFF + 128 * STGS)

__global__ void __launch_bounds__(256) qkv_mma_kernel(const float* __restrict__ x)
{
    extern __shared__ char smem[];
    uint32_t sb = smem_u32(smem);
    uint32_t sWb = sb;

    int tid = threadIdx.x, w = tid >> 5, lane = tid & 31;
    int lr = lane & 7, mi = lane >> 3;
    int row0 = blockIdx.x * 256;   // flat row = (n*2048 + l)*16 + h

    #define CP_X(tt) do { \
        int _t = (tt); \
        uint32_t _xb = sb + XOFF + _t * XBUF; \
        const float* _xs = x + (size_t)(row0 + _t * 128) * 64; \
        _Pragma("unroll") \
        for (int _i = 0; _i < 8; ++_i) { \
            int _g = _i * 256 + tid; \
            int _r = _g >> 4, _c = _g & 15; \
            cpa16(_xb + (uint32_t)(_r * (XSTRIDE * 4) + _c * 16), \
                  _xs + (size_t)_r * 64 + _c * 4); \
        } \
    } while (0)

    // group0: W + x tile0 ; group1: x tile1
    #pragma unroll
    for (int i = 0; i < 6; ++i) {
        int g = i * 256 + tid;
        int m = g >> 9, rr = (g >> 3) & 63, c = g & 7;
        cpa16(sWb + (uint32_t)(m * 8192) + SWZ(rr, c), g_wh + m * 4096 + rr * 64 + c * 8);
    }
    CP_X(0); CP_COMMIT();
    CP_X(1); CP_COMMIT();

    int fr = 16 * w + (lane >> 2);
    int fc = 2 * (lane & 3);
    __half* bases[3] = {g_qh, g_kh, g_vh};

    #pragma unroll 1
    for (int tt = 0; tt < 2; ++tt) {
        if (tt == 0) CP_WAITG(1); else CP_WAITG(0);
        __syncthreads();

        int rowb = row0 + tt * 128;
        int n  = rowb >> 15;
        int l0 = (rowb & 32767) >> 4;

        const float* xp = (const float*)(smem + XOFF + tt * XBUF) + fr * XSTRIDE + fc;
        uint32_t AF[4][4];
        #pragma unroll
        for (int kk = 0; kk < 4; ++kk) {
            float2 v0 = *(const float2*)(xp + 16 * kk);
            float2 v1 = *(const float2*)(xp + 16 * kk + 8 * XSTRIDE);
            float2 v2 = *(const float2*)(xp + 16 * kk + 8);
            float2 v3 = *(const float2*)(xp + 16 * kk + 8 * XSTRIDE + 8);
            AF[kk][0] = packh2(v0.x, v0.y);
            AF[kk][1] = packh2(v1.x, v1.y);
            AF[kk][2] = packh2(v2.x, v2.y);
            AF[kk][3] = packh2(v3.x, v3.y);
        }

        #pragma unroll 1
        for (int m = 0; m < 3; ++m) {
            uint32_t wb = sWb + (uint32_t)(m * 8192);
            #pragma unroll
            for (int j = 0; j < 8; ++j) {
                uint32_t BF[4][2];
                #pragma unroll
                for (int k2 = 0; k2 < 4; k2 += 2) {
                    uint32_t r4[4];
                    ldsm4(r4, wb + SWZ(8 * j + lr, 2 * k2 + mi));
                    BF[k2][0] = r4[0];     BF[k2][1] = r4[1];
                    BF[k2 + 1][0] = r4[2]; BF[k2 + 1][1] = r4[3];
                }
                float Cj[4] = {0.f, 0.f, 0.f, 0.f};
                #pragma unroll
                for (int kk = 0; kk < 4; ++kk)
                    mma_f16(Cj, AF[kk], BF[kk]);
                int col = 8 * j + fc;
                *(uint32_t*)(smem + STG_OFF + fr * STGS + col * 2)       = packh2(Cj[0], Cj[1]);
                *(uint32_t*)(smem + STG_OFF + (fr + 8) * STGS + col * 2) = packh2(Cj[2], Cj[3]);
            }
            __syncthreads();
            __half* base = bases[m];
            #pragma unroll
            for (int i2 = 0; i2 < 4; ++i2) {
                int g = i2 * 256 + tid;
                int r = g >> 3, c = g & 7;
                int h = r & 15, li = r >> 4;
                uint4 v = *(const uint4*)(smem + STG_OFF + r * STGS + c * 16);
                *(uint4*)(base + (((size_t)(n * HH + h) * LL) + (l0 + li)) * DD + c * 8) = v;
            }
            __syncthreads();
        }
    }
    #undef CP_X
}

// =====================================================================
// Kernel 2: fp16 mma.sync flash attention (R14 known-good, 3 CTAs/SM).
// =====================================================================
#define AT_SMEM 65536

__global__ void __launch_bounds__(128, 3) attn_kernel()
{
    extern __shared__ char smem[];
    int tid = threadIdx.x, w = tid >> 5, lane = tid & 31;
    int bh = blockIdx.x, qb = blockIdx.y;
    size_t hbase = (size_t)bh * (LL * DD);
    const __half* qg = g_qh + hbase + (size_t)qb * 128 * DD;
    const __half* kg = g_kh + hbase;
    const __half* vg = g_vh + hbase;

    uint32_t sQb = smem_u32(smem);
    uint32_t sKb = sQb + 16384;
    uint32_t sVb = sQb + 40960;
    int lr = lane & 7, mi = lane >> 3;

    #define CP_KV(t, boff) do { \
        int _t = (t); uint32_t _b = (boff); \
        _Pragma("unroll") \
        for (int _i = 0; _i < 2; ++_i) { \
            int _g = _i * 128 + tid; int _r = _g >> 3, _c = _g & 7; \
            cpa16(sKb + _b + SWZ(_r, _c), kg + ((size_t)_t * 32 + _r) * 64 + _c * 8); \
            cpa16(sVb + _b + SWZ(_r, _c), vg + ((size_t)_t * 32 + _r) * 64 + _c * 8); \
        } \
    } while (0)

    #pragma unroll
    for (int i = 0; i < 8; ++i) {
        int g = i * 128 + tid;
        int r = g >> 3, c = g & 7;
        cpa16(sQb + SWZ(r, c), qg + r * 64 + c * 8);
    }
    CP_KV(0, 0);        CP_COMMIT();
    CP_KV(1, 4096);     CP_COMMIT();
    CP_KV(2, 8192);     CP_COMMIT();
    CP_KV(3, 12288);    CP_COMMIT();

    CP_WAITG(3);
    __syncthreads();

    uint32_t QA[2][4][4];
    #pragma unroll
    for (int i = 0; i < 2; ++i)
        #pragma unroll
        for (int kk = 0; kk < 4; ++kk)
            ldsm4(QA[i][kk], sQb + SWZ(32 * w + 16 * i + (mi & 1) * 8 + lr, 2 * kk + (mi >> 1)));

    float O[2][8][4];
    float O1[2][4];
    #pragma unroll
    for (int i = 0; i < 2; ++i) {
        #pragma unroll
        for (int j = 0; j < 8; ++j)
            #pragma unroll
            for (int c = 0; c < 4; ++c) O[i][j][c] = 0.0f;
        #pragma unroll
        for (int c = 0; c < 4; ++c) O1[i][c] = 0.0f;
    }
    const uint32_t onesr[2] = {ONESH2, ONESH2};

    uint32_t offR = 0, offW = 16384;

    #pragma unroll 2
    for (int t = 0; t < 64; ++t) {
        if (!(t & 1)) { CP_WAITG(2); __syncthreads(); }
        if (t + 4 < 64) CP_KV(t + 4, offW);
        CP_COMMIT();

        uint32_t kb = sKb + offR;
        uint32_t vb = sVb + offR;
        offR += 4096; if (offR == 24576) offR = 0;
        offW += 4096; if (offW == 24576) offW = 0;

        uint32_t PA[2][2][4];
        #pragma unroll
        for (int j = 0; j < 4; ++j) {
            uint32_t BKj[4][2];
            #pragma unroll
            for (int k2 = 0; k2 < 4; k2 += 2) {
                uint32_t r4[4];
                ldsm4(r4, kb + SWZ(8 * j + lr, 2 * k2 + mi));
                BKj[k2][0] = r4[0];     BKj[k2][1] = r4[1];
                BKj[k2 + 1][0] = r4[2]; BKj[k2 + 1][1] = r4[3];
            }
            #pragma unroll
            for (int i = 0; i < 2; ++i) {
                float Sj[4] = {0.f, 0.f, 0.f, 0.f};
                #pragma unroll
                for (int kk = 0; kk < 4; ++kk)
                    mma_f16(Sj, QA[i][kk], BKj[kk]);
                PA[i][j >> 1][(j & 1) * 2 + 0] = ex2h2(packh2(Sj[0], Sj[1]));
                PA[i][j >> 1][(j & 1) * 2 + 1] = ex2h2(packh2(Sj[2], Sj[3]));
            }
        }

        #pragma unroll
        for (int kk = 0; kk < 2; ++kk) {
            #pragma unroll
            for (int j2 = 0; j2 < 8; j2 += 2) {
                uint32_t r4[4];
                ldsm4t(r4, vb + SWZ(16 * kk + (mi & 1) * 8 + lr, j2 + (mi >> 1)));
                uint32_t bva[2] = {r4[0], r4[1]};
                uint32_t bvb[2] = {r4[2], r4[3]};
                #pragma unroll
                for (int i = 0; i < 2; ++i) {
                    mma_f16(O[i][j2],     PA[i][kk], bva);
                    mma_f16(O[i][j2 + 1], PA[i][kk], bvb);
                }
            }
            #pragma unroll
            for (int i = 0; i < 2; ++i)
                mma_f16(O1[i], PA[i][kk], onesr);
        }
    }
    #undef CP_KV

    __syncthreads();
    #pragma unroll
    for (int i = 0; i < 2; ++i) {
        float inv[2] = {1.0f / O1[i][0], 1.0f / O1[i][2]};
        #pragma unroll
        for (int hh = 0; hh < 2; ++hh) {
            int row = 32 * w + 16 * i + 8 * hh + (lane >> 2);
            #pragma unroll
            for (int j = 0; j < 8; ++j) {
                int col = 8 * j + 2 * (lane & 3);
                *(uint32_t*)(smem + row * STGS + col * 2) =
                    packh2(O[i][j][hh * 2 + 0] * inv[hh], O[i][j][hh * 2 + 1] * inv[hh]);
            }
        }
    }
    __syncthreads();

    int n = bh >> 4, h = bh & 15;
    __half* cp = g_ctxh + ((size_t)(n * LL) + (size_t)qb * 128) * EE + h * 64;
    #pragma unroll
    for (int i2 = 0; i2 < 8; ++i2) {
        int g = i2 * 128 + tid;
        int r = g >> 3, c = g & 7;
        uint4 v = *(const uint4*)(smem + r * STGS + c * 16);
        *(uint4*)(cp + (size_t)r * EE + c * 8) = v;
    }
}

// =====================================================================
// Kernel 3: output projection. k64 stages, 2-stage ring (64KB), JIT B
// fragments, __launch_bounds__(128,3) -> 3 CTAs/SM = 3 warps/SMSP.
// =====================================================================
#define OPS_STAGE 32768
#define OP_SMEM   (2 * OPS_STAGE)

__global__ void __launch_bounds__(128, 3) outproj_kernel(
    const float* __restrict__ bo,
    float* __restrict__ out)
{
    extern __shared__ char smp[];

    int tid = threadIdx.x, w = tid >> 5, lane = tid & 31;
    int wm = w >> 1, wn = w & 1;
    int bx = blockIdx.x, by = blockIdx.y;

    const __half* A = g_ctxh + (size_t)(by * 128) * EE;
    const __half* B = g_woh + (size_t)(bx * 128) * EE;
    uint32_t sb = smem_u32(smp);

    #define CP_AB(ks) do { \
        int _k = (ks); uint32_t _b = (uint32_t)(((_k) & 1) * OPS_STAGE); \
        _Pragma("unroll") \
        for (int _i = 0; _i < 16; ++_i) { \
            int _g = _i * 128 + tid; \
            int _gg = _g & 1023; \
            int _r = _gg >> 3, _c = _gg & 7; \
            const __half* _src = (_g < 1024) ? A : B; \
            uint32_t _d = (_g < 1024) ? 0u : 16384u; \
            cpa16(sb + _b + _d + SWZ(_r, _c), _src + (size_t)_r * EE + _k * 64 + _c * 8); \
        } \
    } while (0)

    CP_AB(0); CP_COMMIT();

    float C[4][8][4];
    #pragma unroll
    for (int i = 0; i < 4; ++i)
        #pragma unroll
        for (int j = 0; j < 8; ++j)
            #pragma unroll
            for (int c = 0; c < 4; ++c) C[i][j][c] = 0.0f;

    int lr = lane & 7, mi = lane >> 3;

    #pragma unroll 1
    for (int ks = 0; ks < 16; ++ks) {
        CP_WAITG(0);
        __syncthreads();
        if (ks + 1 < 16) { CP_AB(ks + 1); CP_COMMIT(); }

        uint32_t ab = sb + (uint32_t)((ks & 1) * OPS_STAGE);
        uint32_t bb = ab + 16384;

        #pragma unroll
        for (int hf = 0; hf < 2; ++hf) {
            uint32_t AF[4][2][4];
            #pragma unroll
            for (int i = 0; i < 4; ++i)
                #pragma unroll
                for (int kk = 0; kk < 2; ++kk)
                    ldsm4(AF[i][kk],
                          ab + SWZ(64 * wm + 16 * i + (mi & 1) * 8 + lr, 4 * hf + 2 * kk + (mi >> 1)));

            // JIT B fragments: 4 live regs at a time
            #pragma unroll
            for (int j = 0; j < 8; ++j) {
                uint32_t r4[4];
                ldsm4(r4, bb + SWZ(64 * wn + 8 * j + lr, 4 * hf + mi));
                uint32_t b0[2] = {r4[0], r4[1]};
                uint32_t b1[2] = {r4[2], r4[3]};
                #pragma unroll
                for (int i = 0; i < 4; ++i) {
                    mma_f16(C[i][j], AF[i][0], b0);
                    mma_f16(C[i][j], AF[i][1], b1);
                }
            }
        }
    }
    #undef CP_AB

    float bb2[8][2];
    #pragma unroll
    for (int j = 0; j < 8; ++j) {
        int nn = bx * 128 + 64 * wn + 8 * j + 2 * (lane & 3);
        bb2[j][0] = __ldg(bo + nn);
        bb2[j][1] = __ldg(bo + nn + 1);
    }
    #pragma unroll
    for (int i = 0; i < 4; ++i) {
        int m0 = by * 128 + 64 * wm + 16 * i + (lane >> 2);
        #pragma unroll
        for (int j = 0; j < 8; ++j) {
            int nn = bx * 128 + 64 * wn + 8 * j + 2 * (lane & 3);
            float2 r0 = make_float2(C[i][j][0] + bb2[j][0], C[i][j][1] + bb2[j][1]);
            float2 r1 = make_float2(C[i][j][2] + bb2[j][0], C[i][j][3] + bb2[j][1]);
            *(float2*)(out + (size_t)m0 * EE + nn)       = r0;
            *(float2*)(out + (size_t)(m0 + 8) * EE + nn) = r1;
        }
    }
}

// =====================================================================
extern "C" void kernel_launch(void* const* d_in, const int* in_sizes, int n_in,
                              void* d_out, int out_size)
{
    (void)in_sizes; (void)n_in; (void)out_size;
    const float* x  = (const float*)d_in[0];
    const float* Wq = (const float*)d_in[1];
    const float* Wk = (const float*)d_in[2];
    const float* Wv = (const float*)d_in[3];
    const float* Wo = (const float*)d_in[4];
    const float* bo = (const float*)d_in[5];
    float* out = (float*)d_out;

    cudaFuncSetAttribute(qkv_mma_kernel,
                         cudaFuncAttributeMaxDynamicSharedMemorySize, QKV_SMEM);
    cudaFuncSetAttribute(attn_kernel,
                         cudaFuncAttributeMaxDynamicSharedMemorySize, AT_SMEM);
    cudaFuncSetAttribute(outproj_kernel,
                         cudaFuncAttributeMaxDynamicSharedMemorySize, OP_SMEM);

    convert_kernel<<<1025, 256>>>(Wq, Wk, Wv, Wo);
    qkv_mma_kernel<<<512, 256, QKV_SMEM>>>(x);
    attn_kernel<<<dim3(NB * HH, LL / 128), 128, AT_SMEM>>>();
    outproj_kernel<<<dim3(EE / 128, (NB * LL) / 128), 128, OP_SMEM>>>(bo, out);
}